// round 16
// baseline (speedup 1.0000x reference)
#include <cuda_runtime.h>
#include <math.h>

#define NB 8
#define NGT 100
#define NC 80
#define T_TOTAL 13343
#define NT 256              // threads per block
#define MAXC 128            // max cells per part (level0 <= ~81; lv1-4 <= ~45)
#define IPC 5               // 16-class items per cell
#define PADC 133            // psum row pitch (conflict-spread)

// cross-CTA scratch (device globals: allowed; no allocation)
__device__ double g_lvl[NB * NGT * 5];
__device__ int    g_cnt[NB * NGT];     // parity-based: 2 arrivals per launch

__device__ __forceinline__ float neg_term(float v) {
    float cp = fminf(fmaxf(v, 1e-6f), 1.0f - 1e-6f);
    return (0.75f * (cp * cp)) * (-__logf(1.0f - cp));
}

// ---------------------------------------------------------------------------
// TWO blocks per (batch, gt-box): part 0 = level 0, part 1 = levels 1..4.
// Each part runs the proven 4-phase lazy-s_neg pipeline on its levels and
// writes per-level f64 losses to g_lvl (order-identical to the 12.9us
// kernel). Last-arriving part (atomicAdd parity -> replay-safe, no reset)
// reads all 5 via __ldcg and does the numpy argmin fold.
// ---------------------------------------------------------------------------
__global__ __launch_bounds__(NT) void level_select_kernel(
        const float* __restrict__ cls,
        const float4* __restrict__ regr4,
        const float* __restrict__ gt,
        float* __restrict__ out) {
    const int   fdim_[5] = {100, 50, 25, 13, 7};
    const int   ls_[5]   = {0, 10000, 12500, 13125, 13294};
    const float st_[5]   = {8.f, 16.f, 32.f, 64.f, 128.f};

    int bx   = blockIdx.x;
    int bn   = bx >> 1;                    // box = b*100 + n
    int part = bx & 1;                     // 0: level 0, 1: levels 1..4
    int b    = bn / NGT;
    int tid  = threadIdx.x;
    int lane = tid & 31;
    int wid  = tid >> 5;

    __shared__ int    srx1[4], sry1[4], srnx[4], srcnt[4], spre[5];
    __shared__ int    stc[MAXC];
    __shared__ float  psum[IPC * PADC];
    __shared__ float  sval[MAXC];

    const float* gbox = gt + (size_t)bn * 5;
    float b0 = __ldg(gbox + 0), b1 = __ldg(gbox + 1);
    float b2 = __ldg(gbox + 2), b3 = __ldg(gbox + 3);
    int   label = (int)__ldg(gbox + 4);

    if (!((fabsf(b0) + fabsf(b1) + fabsf(b2) + fabsf(b3)) > 0.0f)) {
        if (part == 0 && tid == 0) out[bn] = -1.0f;   // counter untouched
        return;
    }

    int nlev = part ? 4 : 1;
    int lv0  = part ? 1 : 0;

    const float*  clsb  = cls   + (size_t)b * T_TOTAL * NC;
    const float4* clsb4 = (const float4*)clsb;
    const float4* regb  = regr4 + (size_t)b * T_TOTAL;

    // rect math once per level of this part (exact f32 replica of reference)
    if (tid < nlev) {
        int   l = lv0 + tid;
        float stride = st_[l];
        int   fw = fdim_[l];
        float pb0 = b0 / stride, pb1 = b1 / stride;
        float pb2 = b2 / stride, pb3 = b3 / stride;
        float cx = (pb0 + pb2) * 0.5f, cy = (pb1 + pb3) * 0.5f;
        float hw = ((pb2 - pb0) * 0.2f) * 0.5f;
        float hh = ((pb3 - pb1) * 0.2f) * 0.5f;
        int x1 = (int)fminf(fmaxf(floorf(cx - hw), 0.0f), (float)(fw - 1));
        int y1 = (int)fminf(fmaxf(floorf(cy - hh), 0.0f), (float)(fw - 1));
        int x2 = min(max((int)ceilf(cx + hw), x1 + 1), fw);
        int y2 = min(max((int)ceilf(cy + hh), y1 + 1), fw);
        srx1[tid] = x1; sry1[tid] = y1;
        srnx[tid] = x2 - x1;
        srcnt[tid] = (x2 - x1) * (y2 - y1);
    }
    __syncthreads();

    if (tid == 0) {
        int acc = 0;
        for (int k = 0; k < nlev; k++) { spre[k] = acc; acc += srcnt[k]; }
        spre[nlev] = acc;
    }
    __syncthreads();
    int total = spre[nlev];

    // ---- Phase 0: thread-per-cell mapping; early cp[label]/regr loads ----
    int   myseg = 0, myx = 0, myy = 0;
    float cpl = 0.0f;
    float4 r  = make_float4(0.f, 0.f, 0.f, 0.f);
    if (tid < total) {
        for (int k = 1; k < nlev; k++) if (tid >= spre[k]) myseg = k;
        int l  = lv0 + myseg;
        int c  = tid - spre[myseg];
        int nx = srnx[myseg];
        myx = srx1[myseg] + c % nx;
        myy = sry1[myseg] + c / nx;
        int t = ls_[l] + myy * fdim_[l] + myx;
        stc[tid] = t;
        cpl = clsb[(size_t)t * NC + label];     // in flight across phase 1
        r   = regb[t];                          // in flight across phase 1
    }
    __syncthreads();

    // ---- Phase 1: (cell, 16-class item) grid; 4 indep LDG.128 per item ----
    int items = total * IPC;                    // <= ~405 -> <= 2 volleys
    for (int i = tid; i < items; i += NT) {
        int cell = i / IPC;
        int q    = i - cell * IPC;
        int t    = stc[cell];
        const float4* p = clsb4 + t * (NC / 4) + q * 4;
        float4 v0 = p[0], v1 = p[1], v2 = p[2], v3 = p[3];
        float s = ((neg_term(v0.x) + neg_term(v0.y)) + (neg_term(v0.z) + neg_term(v0.w)))
                + ((neg_term(v1.x) + neg_term(v1.y)) + (neg_term(v1.z) + neg_term(v1.w)))
                + ((neg_term(v2.x) + neg_term(v2.y)) + (neg_term(v2.z) + neg_term(v2.w)))
                + ((neg_term(v3.x) + neg_term(v3.y)) + (neg_term(v3.z) + neg_term(v3.w)));
        psum[q * PADC + cell] = s;
    }
    __syncthreads();

    // ---- Phase 2: thread per cell ----
    if (tid < total) {
        int l = lv0 + myseg;
        float sneg = ((psum[0 * PADC + tid] + psum[1 * PADC + tid])
                   +  (psum[2 * PADC + tid] + psum[3 * PADC + tid]))
                   +   psum[4 * PADC + tid];

        float cp = fminf(fmaxf(cpl, 1e-6f), 1.0f - 1e-6f);
        float om = 1.0f - cp;
        float neg_lab = (0.75f * (cp * cp)) * (-logf(om));
        float pos_lab = (0.25f * (om * om)) * (-logf(cp));

        float stride = st_[l];
        float sx = ((float)myx + 0.5f) * stride;
        float sy = ((float)myy + 0.5f) * stride;
        float tl = (sx - b0) * 0.25f, tt = (sy - b1) * 0.25f;
        float tr = (b2 - sx) * 0.25f, tb = (b3 - sy) * 0.25f;
        float t_area = (tl + tr) * (tt + tb);
        float p_area = (r.x + r.z) * (r.y + r.w);
        float wi = fminf(r.x, tl) + fminf(r.z, tr);
        float hi = fminf(r.y, tt) + fminf(r.w, tb);
        float ai = wi * hi;
        float un = t_area + p_area - ai;
        float iou = -logf((ai + 1.0f) / (un + 1.0f));  // NaN propagates

        sval[tid] = (sneg - neg_lab + pos_lab) + iou;
    }
    __syncthreads();

    // ---- Phase 3: warp w reduces segment w in f64 -> g_lvl (fixed order) ----
    if (wid < nlev) {
        int pre = spre[wid];
        int cnt = srcnt[wid];
        double s = 0.0;
        for (int i = lane; i < cnt; i += 32) s += (double)sval[pre + i];
        #pragma unroll
        for (int o = 16; o; o >>= 1) s += __shfl_down_sync(0xffffffffu, s, o);
        if (lane == 0) g_lvl[(size_t)bn * 5 + lv0 + wid] = s / (double)cnt;
    }
    __syncthreads();

    // ---- last-arriver epilogue (parity counter: replay-safe, no reset) ----
    if (tid == 0) {
        __threadfence();                        // publish g_lvl writes
        int old = atomicAdd(&g_cnt[bn], 1);
        if (old & 1) {                          // second arriver this launch
            __threadfence();                    // acquire peer's g_lvl writes
            double v0 = __ldcg(&g_lvl[(size_t)bn * 5 + 0]);
            double v1 = __ldcg(&g_lvl[(size_t)bn * 5 + 1]);
            double v2 = __ldcg(&g_lvl[(size_t)bn * 5 + 2]);
            double v3 = __ldcg(&g_lvl[(size_t)bn * 5 + 3]);
            double v4 = __ldcg(&g_lvl[(size_t)bn * 5 + 4]);
            // numpy/jax argmin fold: pick if v<best, or v NaN and best not.
            double vals[5] = {v0, v1, v2, v3, v4};
            int    best = 0;
            double bv   = vals[0];
            #pragma unroll
            for (int k = 1; k < 5; k++) {
                double v = vals[k];
                if ((v < bv) || ((v != v) && (bv == bv))) { bv = v; best = k; }
            }
            out[bn] = (float)best;
        }
    }
}

extern "C" void kernel_launch(void* const* d_in, const int* in_sizes, int n_in,
                              void* d_out, int out_size) {
    const float* cls  = (const float*)d_in[0];   // (8, 13343, 80) f32
    const float* regr = (const float*)d_in[1];   // (8, 13343, 4)  f32
    // d_in[2] = feature_shapes (compile-time constants, unused)
    const float* gt   = (const float*)d_in[3];   // (8, 100, 5)    f32
    float* out = (float*)d_out;                  // (8, 100)       f32

    // 2 CTAs per box: part 0 = level 0, part 1 = levels 1..4.
    level_select_kernel<<<NB * NGT * 2, NT>>>(cls, (const float4*)regr, gt, out);
}

// round 17
// speedup vs baseline: 1.1373x; 1.1373x over previous
#include <cuda_runtime.h>
#include <math.h>

#define NB 8
#define NGT 100
#define NC 80
#define T_TOTAL 13343
#define NT 256              // threads per block (R14 proven config)
#define MAXC 128            // max masked cells per box (analytic worst: 123)
#define IPC 5               // items per cell (16 classes each)
#define PADC 133            // psum row pitch (conflict-spread)

__device__ __forceinline__ float neg_term(float v) {
    float cp = fminf(fmaxf(v, 1e-6f), 1.0f - 1e-6f);
    return (0.75f * (cp * cp)) * (-__logf(1.0f - cp));
}

// ---------------------------------------------------------------------------
// One block per (batch, gt-box) — the 12.9us R14 kernel with ONE change:
// cp[label] is no longer loaded separately (123 scattered lines/block);
// it is extracted bit-exactly from phase 1's class loads (the item with
// q == label>>4 holds it) and passed through smem.
// ---------------------------------------------------------------------------
__global__ __launch_bounds__(NT) void level_select_kernel(
        const float* __restrict__ cls,
        const float4* __restrict__ regr4,
        const float* __restrict__ gt,
        float* __restrict__ out) {
    const int   fdim_[5] = {100, 50, 25, 13, 7};
    const int   ls_[5]   = {0, 10000, 12500, 13125, 13294};
    const float st_[5]   = {8.f, 16.f, 32.f, 64.f, 128.f};

    int bn   = blockIdx.x;                 // b*100 + n
    int b    = bn / NGT;
    int tid  = threadIdx.x;
    int lane = tid & 31;
    int wid  = tid >> 5;

    __shared__ int    srx1[5], sry1[5], srnx[5], srcnt[5], spre[6];
    __shared__ int    stc[MAXC];           // cell -> flat location t
    __shared__ float  psum[IPC * PADC];    // [item][cell] neg-focal partials
    __shared__ float  scpl[MAXC];          // cell -> cp[label] (from phase 1)
    __shared__ float  sval[MAXC];          // per-cell total loss
    __shared__ double lvl[5];

    const float* gbox = gt + (size_t)bn * 5;
    float b0 = __ldg(gbox + 0), b1 = __ldg(gbox + 1);
    float b2 = __ldg(gbox + 2), b3 = __ldg(gbox + 3);
    int   label = (int)__ldg(gbox + 4);

    if (!((fabsf(b0) + fabsf(b1) + fabsf(b2) + fabsf(b3)) > 0.0f)) {
        if (tid == 0) out[bn] = -1.0f;
        return;
    }

    const float*  clsb  = cls   + (size_t)b * T_TOTAL * NC;
    const float4* clsb4 = (const float4*)clsb;           // 20 quads per cell
    const float4* regb  = regr4 + (size_t)b * T_TOTAL;

    // rect math ONCE: thread k (<5) computes level k's center-sampling rect
    // (exact f32 replica of the reference)
    if (tid < 5) {
        float stride = st_[tid];
        int   fw = fdim_[tid];
        float pb0 = b0 / stride, pb1 = b1 / stride;
        float pb2 = b2 / stride, pb3 = b3 / stride;
        float cx = (pb0 + pb2) * 0.5f, cy = (pb1 + pb3) * 0.5f;
        float hw = ((pb2 - pb0) * 0.2f) * 0.5f;
        float hh = ((pb3 - pb1) * 0.2f) * 0.5f;
        int x1 = (int)fminf(fmaxf(floorf(cx - hw), 0.0f), (float)(fw - 1));
        int y1 = (int)fminf(fmaxf(floorf(cy - hh), 0.0f), (float)(fw - 1));
        int x2 = min(max((int)ceilf(cx + hw), x1 + 1), fw);
        int y2 = min(max((int)ceilf(cy + hh), y1 + 1), fw);
        srx1[tid] = x1; sry1[tid] = y1;
        srnx[tid] = x2 - x1;
        srcnt[tid] = (x2 - x1) * (y2 - y1);
    }
    __syncthreads();

    if (tid == 0) {
        int acc = 0;
        #pragma unroll
        for (int k = 0; k < 5; k++) { spre[k] = acc; acc += srcnt[k]; }
        spre[5] = acc;
    }
    __syncthreads();
    int total = spre[5];

    // ---- Phase 0: per-cell mapping; issue ONLY the regr load early ----
    int   myl = 0, myx = 0, myy = 0;
    float4 r  = make_float4(0.f, 0.f, 0.f, 0.f);
    if (tid < total) {
        #pragma unroll
        for (int k = 1; k < 5; k++) if (tid >= spre[k]) myl = k;
        int c  = tid - spre[myl];
        int nx = srnx[myl];
        myx = srx1[myl] + c % nx;
        myy = sry1[myl] + c / nx;
        int t = ls_[myl] + myy * fdim_[myl] + myx;
        stc[tid] = t;
        r = regb[t];                        // in flight across phase 1
    }
    __syncthreads();

    // ---- Phase 1: (cell, item) grid; 4 indep LDG.128; label extraction ----
    int items = total * IPC;                    // <= 615 -> <= 3 iterations
    int lab_q = label >> 4;                     // which 16-class item
    int lab_v = (label >> 2) & 3;               // which float4 in the item
    int lab_c = label & 3;                      // which component
    for (int i = tid; i < items; i += NT) {
        int cell = i / IPC;
        int q    = i - cell * IPC;
        int t    = stc[cell];
        const float4* p = clsb4 + t * (NC / 4) + q * 4;
        float4 v0 = p[0], v1 = p[1], v2 = p[2], v3 = p[3];
        float s = ((neg_term(v0.x) + neg_term(v0.y)) + (neg_term(v0.z) + neg_term(v0.w)))
                + ((neg_term(v1.x) + neg_term(v1.y)) + (neg_term(v1.z) + neg_term(v1.w)))
                + ((neg_term(v2.x) + neg_term(v2.y)) + (neg_term(v2.z) + neg_term(v2.w)))
                + ((neg_term(v3.x) + neg_term(v3.y)) + (neg_term(v3.z) + neg_term(v3.w)));
        psum[q * PADC + cell] = s;
        if (q == lab_q) {                       // bit-exact label extraction
            float4 lv = (lab_v == 0) ? v0 : (lab_v == 1) ? v1
                      : (lab_v == 2) ? v2 : v3;
            float cpl = (lab_c == 0) ? lv.x : (lab_c == 1) ? lv.y
                      : (lab_c == 2) ? lv.z : lv.w;
            scpl[cell] = cpl;
        }
    }
    __syncthreads();

    // ---- Phase 2: thread per cell ----
    if (tid < total) {
        float sneg = ((psum[0 * PADC + tid] + psum[1 * PADC + tid])
                   +  (psum[2 * PADC + tid] + psum[3 * PADC + tid]))
                   +   psum[4 * PADC + tid];

        float cp = fminf(fmaxf(scpl[tid], 1e-6f), 1.0f - 1e-6f);
        float om = 1.0f - cp;
        float neg_lab = (0.75f * (cp * cp)) * (-logf(om));
        float pos_lab = (0.25f * (om * om)) * (-logf(cp));

        float stride = st_[myl];
        float sx = ((float)myx + 0.5f) * stride;
        float sy = ((float)myy + 0.5f) * stride;
        float tl = (sx - b0) * 0.25f, tt = (sy - b1) * 0.25f;
        float tr = (b2 - sx) * 0.25f, tb = (b3 - sy) * 0.25f;
        float t_area = (tl + tr) * (tt + tb);
        float p_area = (r.x + r.z) * (r.y + r.w);
        float wi = fminf(r.x, tl) + fminf(r.z, tr);
        float hi = fminf(r.y, tt) + fminf(r.w, tb);
        float ai = wi * hi;
        float un = t_area + p_area - ai;
        float iou = -logf((ai + 1.0f) / (un + 1.0f));  // NaN propagates

        sval[tid] = (sneg - neg_lab + pos_lab) + iou;
    }
    __syncthreads();

    // ---- Phase 3: warp w reduces level w's segment in f64 (fixed order) ----
    if (wid < 5) {
        int pre = spre[wid];
        int cnt = srcnt[wid];
        double s = 0.0;
        for (int i = lane; i < cnt; i += 32) s += (double)sval[pre + i];
        #pragma unroll
        for (int o = 16; o; o >>= 1) s += __shfl_down_sync(0xffffffffu, s, o);
        if (lane == 0) lvl[wid] = s / (double)cnt;
    }
    __syncthreads();

    if (tid == 0) {
        // numpy/jax argmin fold: pick if v<best, or v is NaN and best isn't.
        int    best = 0;
        double bv   = lvl[0];
        #pragma unroll
        for (int k = 1; k < 5; k++) {
            double v = lvl[k];
            if ((v < bv) || ((v != v) && (bv == bv))) { bv = v; best = k; }
        }
        out[bn] = (float)best;
    }
}

extern "C" void kernel_launch(void* const* d_in, const int* in_sizes, int n_in,
                              void* d_out, int out_size) {
    const float* cls  = (const float*)d_in[0];   // (8, 13343, 80) f32
    const float* regr = (const float*)d_in[1];   // (8, 13343, 4)  f32
    // d_in[2] = feature_shapes (compile-time constants, unused)
    const float* gt   = (const float*)d_in[3];   // (8, 100, 5)    f32
    float* out = (float*)d_out;                  // (8, 100)       f32

    level_select_kernel<<<NB * NGT, NT>>>(cls, (const float4*)regr, gt, out);
}